// round 5
// baseline (speedup 1.0000x reference)
#include <cuda_runtime.h>
#include <cuda_bf16.h>
#include <stdint.h>

// Problem constants
#define NN 50000           // nodes
#define NE 800000          // edges
#define NF 256             // in features
#define NH 128             // hidden
#define NC 64              // classes
#define NDROP (NN * NH)    // 6.4M dropout sites

// ---------------- device scratch (static, no runtime allocation) ----------------
__device__ int   g_is64;
__device__ int   g_edges[2 * NE];       // [0..NE) = src, [NE..2NE) = dst
__device__ int   g_counts[NN];          // in-degree (edges only)
__device__ int   g_off[NN + 1];         // CSR offsets
__device__ int   g_cursor[NN];          // fill cursors
__device__ int   g_csr[NE];             // src per incoming edge, grouped by dst
__device__ float g_dinv[NN];            // rsqrt(deg+1)
__device__ float g_H1[NN * NH];         // X @ W1
__device__ float g_A1[NN * NH];         // aggregated + relu + dropout (in place)
__device__ float g_H2[NN * NC];         // A1' @ W2

// ---------------- edge dtype detect + convert ----------------
__global__ void detect_kernel(const unsigned int* e) {
    int is64 = 1;
    for (int i = 0; i < 64; i++) {
        if (e[2 * i + 1] != 0u) { is64 = 0; break; }
    }
    g_is64 = is64;
}

__global__ void convert_kernel(const void* ein) {
    int stride = gridDim.x * blockDim.x;
    int tid = blockIdx.x * blockDim.x + threadIdx.x;
    if (g_is64) {
        const long long* p = (const long long*)ein;
        for (int i = tid; i < 2 * NE; i += stride) g_edges[i] = (int)p[i];
    } else {
        const int* p = (const int*)ein;
        for (int i = tid; i < 2 * NE; i += stride) g_edges[i] = p[i];
    }
}

// ---------------- CSR build ----------------
__global__ void zero_counts_kernel() {
    int tid = blockIdx.x * blockDim.x + threadIdx.x;
    if (tid < NN) g_counts[tid] = 0;
}

__global__ void hist_kernel() {
    int stride = gridDim.x * blockDim.x;
    for (int e = blockIdx.x * blockDim.x + threadIdx.x; e < NE; e += stride) {
        atomicAdd(&g_counts[g_edges[NE + e]], 1);
    }
}

__global__ void scan_kernel() {
    __shared__ int sh[1024];
    const int t = threadIdx.x;
    const int per = (NN + 1023) >> 10;  // 49
    int lo = t * per;
    int hi = lo + per; if (hi > NN) hi = NN;
    if (lo > NN) lo = NN;
    int s = 0;
    for (int i = lo; i < hi; i++) s += g_counts[i];
    sh[t] = s;
    __syncthreads();
    for (int off = 1; off < 1024; off <<= 1) {
        int v = (t >= off) ? sh[t - off] : 0;
        __syncthreads();
        sh[t] += v;
        __syncthreads();
    }
    int base = (t > 0) ? sh[t - 1] : 0;
    for (int i = lo; i < hi; i++) {
        g_off[i] = base;
        g_cursor[i] = base;
        base += g_counts[i];
        g_dinv[i] = rsqrtf((float)(g_counts[i] + 1));
    }
    if (t == 1023) g_off[NN] = sh[1023];
}

__global__ void fill_kernel() {
    int stride = gridDim.x * blockDim.x;
    for (int e = blockIdx.x * blockDim.x + threadIdx.x; e < NE; e += stride) {
        int d = g_edges[NE + e];
        int s = g_edges[e];
        int p = atomicAdd(&g_cursor[d], 1);
        g_csr[p] = s;
    }
}

// ---------------- SGEMM: C[M,BN] = A[M,K] @ W[K,BN] ----------------
template <int BN>
__global__ void gemm_kernel(const float* __restrict__ A, const float* __restrict__ W,
                            float* __restrict__ C, int M, int K) {
    constexpr int BM = 64, BK = 32, THREADS = 256;
    constexpr int CG = BN / 4;          // column groups (float4)
    constexpr int RG = THREADS / CG;    // row groups
    constexpr int RPT = BM / RG;        // rows per thread
    __shared__ float As[BM][BK];
    __shared__ float Ws[BK][BN];

    const int t = threadIdx.x;
    const int c4 = t % CG;
    const int rg = t / CG;
    const int row0 = blockIdx.x * BM;

    float acc[RPT][4];
#pragma unroll
    for (int r = 0; r < RPT; r++) { acc[r][0] = acc[r][1] = acc[r][2] = acc[r][3] = 0.f; }

    for (int kk = 0; kk < K; kk += BK) {
#pragma unroll
        for (int l = 0; l < (BM * BK) / (THREADS * 4); l++) {
            int idx = t + l * THREADS;
            int r = idx / (BK / 4);
            int cc = (idx % (BK / 4)) * 4;
            float4 v = make_float4(0.f, 0.f, 0.f, 0.f);
            if (row0 + r < M) v = *(const float4*)&A[(size_t)(row0 + r) * K + kk + cc];
            *(float4*)&As[r][cc] = v;
        }
#pragma unroll
        for (int l = 0; l < (BK * BN) / (THREADS * 4); l++) {
            int idx = t + l * THREADS;
            int r = idx / (BN / 4);
            int cc = (idx % (BN / 4)) * 4;
            *(float4*)&Ws[r][cc] = *(const float4*)&W[(size_t)(kk + r) * BN + cc];
        }
        __syncthreads();
#pragma unroll
        for (int kr = 0; kr < BK; kr++) {
            float4 w = *(const float4*)&Ws[kr][c4 * 4];
#pragma unroll
            for (int r = 0; r < RPT; r++) {
                float a = As[rg * RPT + r][kr];
                acc[r][0] += a * w.x;
                acc[r][1] += a * w.y;
                acc[r][2] += a * w.z;
                acc[r][3] += a * w.w;
            }
        }
        __syncthreads();
    }
#pragma unroll
    for (int r = 0; r < RPT; r++) {
        int row = row0 + rg * RPT + r;
        if (row < M) {
            float4 v = make_float4(acc[r][0], acc[r][1], acc[r][2], acc[r][3]);
            *(float4*)&C[(size_t)row * BN + c4 * 4] = v;
        }
    }
}

// ---------------- normalized gather (layer 1: 128 features, float4/lane) ----------------
__global__ void gather128_kernel(const float* __restrict__ H, float* __restrict__ out) {
    int gwarp = (blockIdx.x * blockDim.x + threadIdx.x) >> 5;
    int lane = threadIdx.x & 31;
    int nwarp = (gridDim.x * blockDim.x) >> 5;
    const float4* H4 = (const float4*)H;
    for (int d = gwarp; d < NN; d += nwarp) {
        float dd = g_dinv[d];
        float w0 = dd * dd;
        float4 hv = H4[(size_t)d * 32 + lane];
        float4 acc = make_float4(w0 * hv.x, w0 * hv.y, w0 * hv.z, w0 * hv.w);
        int s0 = g_off[d], s1 = g_off[d + 1];
        for (int i = s0; i < s1; i++) {
            int s = g_csr[i];
            float w = dd * g_dinv[s];
            float4 v = H4[(size_t)s * 32 + lane];
            acc.x += w * v.x; acc.y += w * v.y; acc.z += w * v.z; acc.w += w * v.w;
        }
        ((float4*)out)[(size_t)d * 32 + lane] = acc;
    }
}

// ---------------- normalized gather (layer 2: 64 features, float2/lane) + bias -> d_out ----------------
__global__ void gather64_kernel(const float* __restrict__ H, const float* __restrict__ b,
                                float* __restrict__ out) {
    int gwarp = (blockIdx.x * blockDim.x + threadIdx.x) >> 5;
    int lane = threadIdx.x & 31;
    int nwarp = (gridDim.x * blockDim.x) >> 5;
    const float2* H2 = (const float2*)H;
    for (int d = gwarp; d < NN; d += nwarp) {
        float dd = g_dinv[d];
        float w0 = dd * dd;
        float2 hv = H2[(size_t)d * 32 + lane];
        float2 acc = make_float2(w0 * hv.x, w0 * hv.y);
        int s0 = g_off[d], s1 = g_off[d + 1];
        for (int i = s0; i < s1; i++) {
            int s = g_csr[i];
            float w = dd * g_dinv[s];
            float2 v = H2[(size_t)s * 32 + lane];
            acc.x += w * v.x; acc.y += w * v.y;
        }
        acc.x += b[lane * 2];
        acc.y += b[lane * 2 + 1];
        ((float2*)out)[(size_t)d * 32 + lane] = acc;
    }
}

// ---------------- Threefry-2x32 + relu + dropout ----------------
__device__ __forceinline__ unsigned int rotl32(unsigned int x, int d) {
    return (x << d) | (x >> (32 - d));
}

__device__ __forceinline__ void threefry2x32(unsigned int k0, unsigned int k1,
                                             unsigned int x0, unsigned int x1,
                                             unsigned int& o0, unsigned int& o1) {
    unsigned int ks0 = k0, ks1 = k1, ks2 = k0 ^ k1 ^ 0x1BD11BDAu;
    x0 += ks0; x1 += ks1;
#define TF_R4(a, b, c, d)                                 \
    x0 += x1; x1 = rotl32(x1, a); x1 ^= x0;               \
    x0 += x1; x1 = rotl32(x1, b); x1 ^= x0;               \
    x0 += x1; x1 = rotl32(x1, c); x1 ^= x0;               \
    x0 += x1; x1 = rotl32(x1, d); x1 ^= x0;
    TF_R4(13, 15, 26, 6);  x0 += ks1; x1 += ks2 + 1u;
    TF_R4(17, 29, 16, 24); x0 += ks2; x1 += ks0 + 2u;
    TF_R4(13, 15, 26, 6);  x0 += ks0; x1 += ks1 + 3u;
    TF_R4(17, 29, 16, 24); x0 += ks1; x1 += ks2 + 4u;
    TF_R4(13, 15, 26, 6);  x0 += ks2; x1 += ks0 + 5u;
#undef TF_R4
    o0 = x0; o1 = x1;
}

// JAX defaults: threefry_partitionable=True, x64 OFF (consistent with int64->int32
// demotion of edge_index). bernoulli -> uniform(float32) -> random_bits(32):
//   counts = iota(uint64, n); (bits1, bits2) = threefry2x32(key=(0,42), (hi32=0, lo32=j))
//   32-bit output = bits1 ^ bits2
//   keep = u < 0.5  <=>  bit31(bits1 ^ bits2) == 0.
__global__ void relu_dropout_kernel(float* __restrict__ h, const float* __restrict__ b) {
    int stride = gridDim.x * blockDim.x;
    for (int j = blockIdx.x * blockDim.x + threadIdx.x; j < NDROP; j += stride) {
        unsigned int o0, o1;
        threefry2x32(0u, 42u, 0u, (unsigned int)j, o0, o1);
        float v = h[j] + b[j & 127];
        v = fmaxf(v, 0.f);
        h[j] = ((o0 ^ o1) & 0x80000000u) ? 0.f : 2.f * v;
    }
}

// ---------------- launch ----------------
extern "C" void kernel_launch(void* const* d_in, const int* in_sizes, int n_in,
                              void* d_out, int out_size) {
    // Map inputs by element count (all distinct) — robust to ordering.
    const float* x  = 0; const void* ei = 0;
    const float* W1 = 0; const float* b1 = 0;
    const float* W2 = 0; const float* b2 = 0;
    for (int i = 0; i < n_in; i++) {
        switch (in_sizes[i]) {
            case NN * NF:  x  = (const float*)d_in[i]; break;  // 12.8M
            case 2 * NE:   ei = d_in[i];               break;  // 1.6M
            case NF * NH:  W1 = (const float*)d_in[i]; break;  // 32768
            case NH:       b1 = (const float*)d_in[i]; break;  // 128
            case NH * NC:  W2 = (const float*)d_in[i]; break;  // 8192
            case NC:       b2 = (const float*)d_in[i]; break;  // 64
        }
    }
    float* out = (float*)d_out;

    float* H1; cudaGetSymbolAddress((void**)&H1, g_H1);
    float* A1; cudaGetSymbolAddress((void**)&A1, g_A1);
    float* H2; cudaGetSymbolAddress((void**)&H2, g_H2);

    detect_kernel<<<1, 1>>>((const unsigned int*)ei);
    convert_kernel<<<2048, 256>>>(ei);

    zero_counts_kernel<<<(NN + 255) / 256, 256>>>();
    hist_kernel<<<1024, 256>>>();
    scan_kernel<<<1, 1024>>>();
    fill_kernel<<<1024, 256>>>();

    gemm_kernel<NH><<<(NN + 63) / 64, 256>>>(x, W1, H1, NN, NF);
    gather128_kernel<<<1024, 256>>>(H1, A1);
    relu_dropout_kernel<<<4096, 256>>>(A1, b1);
    gemm_kernel<NC><<<(NN + 63) / 64, 256>>>(A1, W2, H2, NN, NH);
    gather64_kernel<<<1024, 256>>>(H2, b2, out);
}

// round 6
// speedup vs baseline: 1.0615x; 1.0615x over previous
#include <cuda_runtime.h>
#include <cuda_bf16.h>
#include <stdint.h>

// Problem constants
#define NN 50000           // nodes
#define NE 800000          // edges
#define NF 256             // in features
#define NH 128             // hidden
#define NC 64              // classes
#define NDROP (NN * NH)    // 6.4M dropout sites

// ---------------- device scratch (static, no runtime allocation) ----------------
__device__ int   g_edges[2 * NE];       // [0..NE) = src, [NE..2NE) = dst
__device__ int   g_counts[NN];          // in-degree (edges only)
__device__ int   g_off[NN + 1];         // CSR offsets
__device__ int   g_cursor[NN];          // fill cursors
__device__ int   g_csr[NE];             // src per incoming edge, grouped by dst
__device__ float g_dinv[NN];            // rsqrt(deg+1)
__device__ float g_H1[NN * NH];         // X @ W1
__device__ float g_A1[NN * NH];         // aggregated + bias + relu + dropout
__device__ float g_H2[NN * NC];         // A1 @ W2

// ---------------- zero counts ----------------
__global__ void zero_counts_kernel() {
    int tid = blockIdx.x * blockDim.x + threadIdx.x;
    if (tid < NN) g_counts[tid] = 0;
}

// ---------------- convert (+local dtype detect) + histogram, fused ----------------
__global__ void convert_hist_kernel(const void* ein) {
    // Local detect: int64 edges => high words all zero (values < 50000 < 2^31).
    const unsigned int* e32 = (const unsigned int*)ein;
    bool is64 = true;
#pragma unroll 8
    for (int i = 0; i < 64; i++) {
        if (e32[2 * i + 1] != 0u) { is64 = false; break; }
    }
    int stride = gridDim.x * blockDim.x;
    int tid = blockIdx.x * blockDim.x + threadIdx.x;
    if (is64) {
        const long long* p = (const long long*)ein;
        for (int i = tid; i < 2 * NE; i += stride) {
            int v = (int)p[i];
            g_edges[i] = v;
            if (i >= NE) atomicAdd(&g_counts[v], 1);
        }
    } else {
        const int* p = (const int*)ein;
        for (int i = tid; i < 2 * NE; i += stride) {
            int v = p[i];
            g_edges[i] = v;
            if (i >= NE) atomicAdd(&g_counts[v], 1);
        }
    }
}

// ---------------- single-block scan -> offsets, cursors, dinv ----------------
__global__ void scan_kernel() {
    __shared__ int sh[1024];
    const int t = threadIdx.x;
    const int per = (NN + 1023) >> 10;  // 49
    int lo = t * per;
    int hi = lo + per; if (hi > NN) hi = NN;
    if (lo > NN) lo = NN;
    int s = 0;
    for (int i = lo; i < hi; i++) s += g_counts[i];
    sh[t] = s;
    __syncthreads();
    for (int off = 1; off < 1024; off <<= 1) {
        int v = (t >= off) ? sh[t - off] : 0;
        __syncthreads();
        sh[t] += v;
        __syncthreads();
    }
    int base = (t > 0) ? sh[t - 1] : 0;
    for (int i = lo; i < hi; i++) {
        g_off[i] = base;
        g_cursor[i] = base;
        base += g_counts[i];
        g_dinv[i] = rsqrtf((float)(g_counts[i] + 1));
    }
    if (t == 1023) g_off[NN] = sh[1023];
}

__global__ void fill_kernel() {
    int stride = gridDim.x * blockDim.x;
    for (int e = blockIdx.x * blockDim.x + threadIdx.x; e < NE; e += stride) {
        int d = g_edges[NE + e];
        int s = g_edges[e];
        int p = atomicAdd(&g_cursor[d], 1);
        g_csr[p] = s;
    }
}

// ---------------- SGEMM with packed f32x2 FMA ----------------
// C[M,BN] = A[M,K] @ W[K,BN].  BM=128, BK=16, 256 threads, 8x8 micro-tile.
// Thread (tx,ty): rows {ty*4+r, 64+ty*4+r}, cols {c*64 + tx*4 .. +3} for c<NW.
template <int BN>
__global__ __launch_bounds__(256) void gemm_f32x2_kernel(
    const float* __restrict__ A, const float* __restrict__ W,
    float* __restrict__ C, int M, int K)
{
    constexpr int BM = 128, BK = 16;
    constexpr int NW = BN / 64;        // n-chunks of 64 (2 for BN=128, 1 for BN=64)
    __shared__ float As[BK][BM];       // transposed A tile
    __shared__ float Ws[BK][BN];

    const int t = threadIdx.x;
    const int tx = t & 15;             // n group (16)
    const int ty = t >> 4;             // m group (16)
    const int row0 = blockIdx.x * BM;

    unsigned long long acc[2][4][NW][2];  // f32x2 pairs
#pragma unroll
    for (int mc = 0; mc < 2; mc++)
#pragma unroll
        for (int r = 0; r < 4; r++)
#pragma unroll
            for (int c = 0; c < NW; c++) {
                acc[mc][r][c][0] = 0ull;
                acc[mc][r][c][1] = 0ull;
            }

    for (int kk = 0; kk < K; kk += BK) {
        // A tile (transpose): 2048 floats = 512 float4, 2 per thread.
#pragma unroll
        for (int l = 0; l < 2; l++) {
            int idx = l * 256 + t;
            int r = idx >> 2;               // 0..127
            int kq = (idx & 3) * 4;         // 0,4,8,12
            float4 v = make_float4(0.f, 0.f, 0.f, 0.f);
            if (row0 + r < M) v = *(const float4*)&A[(size_t)(row0 + r) * K + kk + kq];
            As[kq + 0][r] = v.x; As[kq + 1][r] = v.y;
            As[kq + 2][r] = v.z; As[kq + 3][r] = v.w;
        }
        // W tile: BK*BN floats.
#pragma unroll
        for (int l = 0; l < NW; l++) {
            int idx = l * 256 + t;
            int r = idx / (BN / 4);
            int c = idx % (BN / 4);
            *(float4*)&Ws[r][c * 4] = *(const float4*)&W[(size_t)(kk + r) * BN + c * 4];
        }
        __syncthreads();

#pragma unroll
        for (int kr = 0; kr < BK; kr++) {
            float4 a0 = *(const float4*)&As[kr][ty * 4];
            float4 a1 = *(const float4*)&As[kr][64 + ty * 4];
            unsigned long long w[NW][2];
#pragma unroll
            for (int c = 0; c < NW; c++) {
                ulonglong2 wv = *(const ulonglong2*)&Ws[kr][c * 64 + tx * 4];
                w[c][0] = wv.x; w[c][1] = wv.y;
            }
            float am[8] = {a0.x, a0.y, a0.z, a0.w, a1.x, a1.y, a1.z, a1.w};
#pragma unroll
            for (int r = 0; r < 8; r++) {
                unsigned int au = __float_as_uint(am[r]);
                unsigned long long a2;
                asm("mov.b64 %0, {%1, %1};" : "=l"(a2) : "r"(au));
#pragma unroll
                for (int c = 0; c < NW; c++) {
                    asm("fma.rn.f32x2 %0, %1, %2, %0;"
                        : "+l"(acc[r >> 2][r & 3][c][0]) : "l"(a2), "l"(w[c][0]));
                    asm("fma.rn.f32x2 %0, %1, %2, %0;"
                        : "+l"(acc[r >> 2][r & 3][c][1]) : "l"(a2), "l"(w[c][1]));
                }
            }
        }
        __syncthreads();
    }

#pragma unroll
    for (int mc = 0; mc < 2; mc++)
#pragma unroll
        for (int r = 0; r < 4; r++) {
            int row = row0 + mc * 64 + ty * 4 + r;
            if (row < M) {
#pragma unroll
                for (int c = 0; c < NW; c++) {
                    unsigned int u0, u1, u2, u3;
                    asm("mov.b64 {%0, %1}, %2;" : "=r"(u0), "=r"(u1) : "l"(acc[mc][r][c][0]));
                    asm("mov.b64 {%0, %1}, %2;" : "=r"(u2), "=r"(u3) : "l"(acc[mc][r][c][1]));
                    float4 v = make_float4(__uint_as_float(u0), __uint_as_float(u1),
                                           __uint_as_float(u2), __uint_as_float(u3));
                    *(float4*)&C[(size_t)row * BN + c * 64 + tx * 4] = v;
                }
            }
        }
}

// ---------------- Threefry-2x32 ----------------
__device__ __forceinline__ unsigned int rotl32(unsigned int x, int d) {
    return (x << d) | (x >> (32 - d));
}

__device__ __forceinline__ void threefry2x32(unsigned int k0, unsigned int k1,
                                             unsigned int x0, unsigned int x1,
                                             unsigned int& o0, unsigned int& o1) {
    unsigned int ks0 = k0, ks1 = k1, ks2 = k0 ^ k1 ^ 0x1BD11BDAu;
    x0 += ks0; x1 += ks1;
#define TF_R4(a, b, c, d)                                 \
    x0 += x1; x1 = rotl32(x1, a); x1 ^= x0;               \
    x0 += x1; x1 = rotl32(x1, b); x1 ^= x0;               \
    x0 += x1; x1 = rotl32(x1, c); x1 ^= x0;               \
    x0 += x1; x1 = rotl32(x1, d); x1 ^= x0;
    TF_R4(13, 15, 26, 6);  x0 += ks1; x1 += ks2 + 1u;
    TF_R4(17, 29, 16, 24); x0 += ks2; x1 += ks0 + 2u;
    TF_R4(13, 15, 26, 6);  x0 += ks0; x1 += ks1 + 3u;
    TF_R4(17, 29, 16, 24); x0 += ks1; x1 += ks2 + 4u;
    TF_R4(13, 15, 26, 6);  x0 += ks2; x1 += ks0 + 5u;
#undef TF_R4
    o0 = x0; o1 = x1;
}

// keep[j] (JAX default: threefry_partitionable, 32-bit):
//   (b1,b2) = threefry2x32((0,42), (0,j)); keep iff bit31(b1^b2)==0.
__device__ __forceinline__ bool drop_keep(unsigned int j) {
    unsigned int o0, o1;
    threefry2x32(0u, 42u, 0u, j, o0, o1);
    return ((o0 ^ o1) & 0x80000000u) == 0u;
}

// ---------------- gather layer1 (128 feats, float4/lane) + bias + relu + dropout ----------------
__global__ void gather128_fused_kernel(const float* __restrict__ H,
                                       const float* __restrict__ b,
                                       float* __restrict__ out) {
    int gwarp = (blockIdx.x * blockDim.x + threadIdx.x) >> 5;
    int lane = threadIdx.x & 31;
    int nwarp = (gridDim.x * blockDim.x) >> 5;
    const float4* H4 = (const float4*)H;
    float4 bv = ((const float4*)b)[lane];
    for (int d = gwarp; d < NN; d += nwarp) {
        float dd = g_dinv[d];
        float w0 = dd * dd;
        float4 hv = H4[(size_t)d * 32 + lane];
        float4 acc = make_float4(w0 * hv.x, w0 * hv.y, w0 * hv.z, w0 * hv.w);
        int s0 = g_off[d], s1 = g_off[d + 1];
        for (int i = s0; i < s1; i++) {
            int s = g_csr[i];
            float w = dd * g_dinv[s];
            float4 v = H4[(size_t)s * 32 + lane];
            acc.x += w * v.x; acc.y += w * v.y; acc.z += w * v.z; acc.w += w * v.w;
        }
        // epilogue: + b1, relu, dropout(p=0.5, x2 on keep)
        unsigned int j = (unsigned int)d * 128u + (unsigned int)lane * 4u;
        acc.x = fmaxf(acc.x + bv.x, 0.f);
        acc.y = fmaxf(acc.y + bv.y, 0.f);
        acc.z = fmaxf(acc.z + bv.z, 0.f);
        acc.w = fmaxf(acc.w + bv.w, 0.f);
        acc.x = drop_keep(j + 0u) ? 2.f * acc.x : 0.f;
        acc.y = drop_keep(j + 1u) ? 2.f * acc.y : 0.f;
        acc.z = drop_keep(j + 2u) ? 2.f * acc.z : 0.f;
        acc.w = drop_keep(j + 3u) ? 2.f * acc.w : 0.f;
        ((float4*)out)[(size_t)d * 32 + lane] = acc;
    }
}

// ---------------- gather layer2 (64 feats, float2/lane) + b2 -> d_out ----------------
__global__ void gather64_kernel(const float* __restrict__ H, const float* __restrict__ b,
                                float* __restrict__ out) {
    int gwarp = (blockIdx.x * blockDim.x + threadIdx.x) >> 5;
    int lane = threadIdx.x & 31;
    int nwarp = (gridDim.x * blockDim.x) >> 5;
    const float2* H2 = (const float2*)H;
    for (int d = gwarp; d < NN; d += nwarp) {
        float dd = g_dinv[d];
        float w0 = dd * dd;
        float2 hv = H2[(size_t)d * 32 + lane];
        float2 acc = make_float2(w0 * hv.x, w0 * hv.y);
        int s0 = g_off[d], s1 = g_off[d + 1];
        for (int i = s0; i < s1; i++) {
            int s = g_csr[i];
            float w = dd * g_dinv[s];
            float2 v = H2[(size_t)s * 32 + lane];
            acc.x += w * v.x; acc.y += w * v.y;
        }
        acc.x += b[lane * 2];
        acc.y += b[lane * 2 + 1];
        ((float2*)out)[(size_t)d * 32 + lane] = acc;
    }
}

// ---------------- launch ----------------
extern "C" void kernel_launch(void* const* d_in, const int* in_sizes, int n_in,
                              void* d_out, int out_size) {
    // Map inputs by element count (all distinct).
    const float* x  = 0; const void* ei = 0;
    const float* W1 = 0; const float* b1 = 0;
    const float* W2 = 0; const float* b2 = 0;
    for (int i = 0; i < n_in; i++) {
        switch (in_sizes[i]) {
            case NN * NF:  x  = (const float*)d_in[i]; break;  // 12.8M
            case 2 * NE:   ei = d_in[i];               break;  // 1.6M
            case NF * NH:  W1 = (const float*)d_in[i]; break;  // 32768
            case NH:       b1 = (const float*)d_in[i]; break;  // 128
            case NH * NC:  W2 = (const float*)d_in[i]; break;  // 8192
            case NC:       b2 = (const float*)d_in[i]; break;  // 64
        }
    }
    float* out = (float*)d_out;

    float* H1; cudaGetSymbolAddress((void**)&H1, g_H1);
    float* A1; cudaGetSymbolAddress((void**)&A1, g_A1);
    float* H2; cudaGetSymbolAddress((void**)&H2, g_H2);

    zero_counts_kernel<<<(NN + 255) / 256, 256>>>();
    convert_hist_kernel<<<2048, 256>>>(ei);
    scan_kernel<<<1, 1024>>>();
    fill_kernel<<<1024, 256>>>();

    gemm_f32x2_kernel<NH><<<(NN + 127) / 128, 256>>>(x, W1, H1, NN, NF);
    gather128_fused_kernel<<<2048, 256>>>(H1, b1, A1);
    gemm_f32x2_kernel<NC><<<(NN + 127) / 128, 256>>>(A1, W2, H2, NN, NH);
    gather64_kernel<<<1024, 256>>>(H2, b2, out);
}

// round 7
// speedup vs baseline: 1.1026x; 1.0387x over previous
#include <cuda_runtime.h>
#include <cuda_bf16.h>
#include <stdint.h>

// Problem constants
#define NN 50000           // nodes
#define NE 800000          // edges
#define NF 256             // in features
#define NH 128             // hidden
#define NC 64              // classes

// ---------------- device scratch (static, no runtime allocation) ----------------
__device__ int   g_edges[2 * NE];       // [0..NE) = src, [NE..2NE) = dst
__device__ int   g_counts[NN];          // in-degree (edges only)
__device__ int   g_off[NN + 1];         // CSR offsets
__device__ int   g_cursor[NN];          // fill cursors
__device__ int   g_csr[NE];             // src per incoming edge, grouped by dst
__device__ float g_csrw[NE];            // dinv[src] per csr entry
__device__ float g_dinv[NN];            // rsqrt(deg+1)
__device__ float g_H1[NN * NH];         // X @ W1
__device__ float g_A1[NN * NH];         // aggregated + bias + relu + dropout
__device__ float g_H2[NN * NC];         // A1 @ W2

// ---------------- zero counts ----------------
__global__ void zero_counts_kernel() {
    int tid = blockIdx.x * blockDim.x + threadIdx.x;
    if (tid < NN) g_counts[tid] = 0;
}

// ---------------- convert (+local dtype detect) + histogram, fused ----------------
__global__ void convert_hist_kernel(const void* ein) {
    // int64 edges => high words all zero (values < 50000 < 2^31).
    const unsigned int* e32 = (const unsigned int*)ein;
    bool is64 = true;
#pragma unroll 8
    for (int i = 0; i < 64; i++) {
        if (e32[2 * i + 1] != 0u) { is64 = false; break; }
    }
    int stride = gridDim.x * blockDim.x;
    int tid = blockIdx.x * blockDim.x + threadIdx.x;
    if (is64) {
        const long long* p = (const long long*)ein;
        for (int i = tid; i < 2 * NE; i += stride) {
            int v = (int)p[i];
            g_edges[i] = v;
            if (i >= NE) atomicAdd(&g_counts[v], 1);
        }
    } else {
        const int* p = (const int*)ein;
        for (int i = tid; i < 2 * NE; i += stride) {
            int v = p[i];
            g_edges[i] = v;
            if (i >= NE) atomicAdd(&g_counts[v], 1);
        }
    }
}

// ---------------- single-block scan -> offsets, cursors, dinv ----------------
__global__ void scan_kernel() {
    __shared__ int sh[1024];
    const int t = threadIdx.x;
    const int per = (NN + 1023) >> 10;  // 49
    int lo = t * per;
    int hi = lo + per; if (hi > NN) hi = NN;
    if (lo > NN) lo = NN;
    int s = 0;
    for (int i = lo; i < hi; i++) s += g_counts[i];
    sh[t] = s;
    __syncthreads();
    for (int off = 1; off < 1024; off <<= 1) {
        int v = (t >= off) ? sh[t - off] : 0;
        __syncthreads();
        sh[t] += v;
        __syncthreads();
    }
    int base = (t > 0) ? sh[t - 1] : 0;
    for (int i = lo; i < hi; i++) {
        g_off[i] = base;
        g_cursor[i] = base;
        base += g_counts[i];
        g_dinv[i] = rsqrtf((float)(g_counts[i] + 1));
    }
    if (t == 1023) g_off[NN] = sh[1023];
}

// ---------------- fill: also records dinv[src] per entry ----------------
__global__ void fill_kernel() {
    int stride = gridDim.x * blockDim.x;
    for (int e = blockIdx.x * blockDim.x + threadIdx.x; e < NE; e += stride) {
        int d = g_edges[NE + e];
        int s = g_edges[e];
        int p = atomicAdd(&g_cursor[d], 1);
        g_csr[p] = s;
        g_csrw[p] = g_dinv[s];
    }
}

// ---------------- SGEMM, f32x2 packed FMA, double-buffered smem ----------------
// C[M,BN] = A[M,K] @ W[K,BN]. BM=128, BK=16, 256 threads, 8x8 micro-tile/thread.
template <int BN>
__global__ __launch_bounds__(256) void gemm_f32x2_kernel(
    const float* __restrict__ A, const float* __restrict__ W,
    float* __restrict__ C, int M, int K)
{
    constexpr int BM = 128, BK = 16;
    constexpr int NW = BN / 64;        // 2 for BN=128, 1 for BN=64
    __shared__ float As[2][BK][BM];    // transposed A tile
    __shared__ float Ws[2][BK][BN];

    const int t = threadIdx.x;
    const int tx = t & 15;
    const int ty = t >> 4;
    const int row0 = blockIdx.x * BM;

    // A-tile reg staging: idx = l*256+t -> row r=idx>>2, kq=(idx&3)*4
    const int ar0 = t >> 2, akq = (t & 3) * 4;       // l=0
    const int ar1 = (256 + t) >> 2;                  // l=1 (same kq)
    // W-tile: idx = l*256+t -> r=idx/(BN/4), c=idx%(BN/4)
    float4 pa[2];
    float4 pw[NW];

    unsigned long long acc[2][4][NW][2];
#pragma unroll
    for (int mc = 0; mc < 2; mc++)
#pragma unroll
        for (int r = 0; r < 4; r++)
#pragma unroll
            for (int c = 0; c < NW; c++) { acc[mc][r][c][0] = 0ull; acc[mc][r][c][1] = 0ull; }

    auto load_regs = [&](int kk) {
        pa[0] = make_float4(0.f, 0.f, 0.f, 0.f);
        pa[1] = make_float4(0.f, 0.f, 0.f, 0.f);
        if (row0 + ar0 < M) pa[0] = *(const float4*)&A[(size_t)(row0 + ar0) * K + kk + akq];
        if (row0 + ar1 < M) pa[1] = *(const float4*)&A[(size_t)(row0 + ar1) * K + kk + akq];
#pragma unroll
        for (int l = 0; l < NW; l++) {
            int idx = l * 256 + t;
            int r = idx / (BN / 4);
            int c = idx % (BN / 4);
            pw[l] = *(const float4*)&W[(size_t)(kk + r) * BN + c * 4];
        }
    };
    auto store_smem = [&](int buf) {
        As[buf][akq + 0][ar0] = pa[0].x; As[buf][akq + 1][ar0] = pa[0].y;
        As[buf][akq + 2][ar0] = pa[0].z; As[buf][akq + 3][ar0] = pa[0].w;
        As[buf][akq + 0][ar1] = pa[1].x; As[buf][akq + 1][ar1] = pa[1].y;
        As[buf][akq + 2][ar1] = pa[1].z; As[buf][akq + 3][ar1] = pa[1].w;
#pragma unroll
        for (int l = 0; l < NW; l++) {
            int idx = l * 256 + t;
            int r = idx / (BN / 4);
            int c = idx % (BN / 4);
            *(float4*)&Ws[buf][r][c * 4] = pw[l];
        }
    };

    load_regs(0);
    store_smem(0);
    __syncthreads();

    const int nsteps = K / BK;
    int buf = 0;
    for (int step = 0; step < nsteps; step++) {
        int kk_next = (step + 1) * BK;
        bool more = (kk_next < K);
        if (more) load_regs(kk_next);

#pragma unroll
        for (int kr = 0; kr < BK; kr++) {
            float4 a0 = *(const float4*)&As[buf][kr][ty * 4];
            float4 a1 = *(const float4*)&As[buf][kr][64 + ty * 4];
            unsigned long long w[NW][2];
#pragma unroll
            for (int c = 0; c < NW; c++) {
                ulonglong2 wv = *(const ulonglong2*)&Ws[buf][kr][c * 64 + tx * 4];
                w[c][0] = wv.x; w[c][1] = wv.y;
            }
            float am[8] = {a0.x, a0.y, a0.z, a0.w, a1.x, a1.y, a1.z, a1.w};
#pragma unroll
            for (int r = 0; r < 8; r++) {
                unsigned int au = __float_as_uint(am[r]);
                unsigned long long a2;
                asm("mov.b64 %0, {%1, %1};" : "=l"(a2) : "r"(au));
#pragma unroll
                for (int c = 0; c < NW; c++) {
                    asm("fma.rn.f32x2 %0, %1, %2, %0;"
                        : "+l"(acc[r >> 2][r & 3][c][0]) : "l"(a2), "l"(w[c][0]));
                    asm("fma.rn.f32x2 %0, %1, %2, %0;"
                        : "+l"(acc[r >> 2][r & 3][c][1]) : "l"(a2), "l"(w[c][1]));
                }
            }
        }
        if (more) store_smem(buf ^ 1);
        __syncthreads();
        buf ^= 1;
    }

#pragma unroll
    for (int mc = 0; mc < 2; mc++)
#pragma unroll
        for (int r = 0; r < 4; r++) {
            int row = row0 + mc * 64 + ty * 4 + r;
            if (row < M) {
#pragma unroll
                for (int c = 0; c < NW; c++) {
                    unsigned int u0, u1, u2, u3;
                    asm("mov.b64 {%0, %1}, %2;" : "=r"(u0), "=r"(u1) : "l"(acc[mc][r][c][0]));
                    asm("mov.b64 {%0, %1}, %2;" : "=r"(u2), "=r"(u3) : "l"(acc[mc][r][c][1]));
                    float4 v = make_float4(__uint_as_float(u0), __uint_as_float(u1),
                                           __uint_as_float(u2), __uint_as_float(u3));
                    *(float4*)&C[(size_t)row * BN + c * 64 + tx * 4] = v;
                }
            }
        }
}

// ---------------- Threefry-2x32 ----------------
__device__ __forceinline__ unsigned int rotl32(unsigned int x, int d) {
    return (x << d) | (x >> (32 - d));
}

__device__ __forceinline__ void threefry2x32(unsigned int k0, unsigned int k1,
                                             unsigned int x0, unsigned int x1,
                                             unsigned int& o0, unsigned int& o1) {
    unsigned int ks0 = k0, ks1 = k1, ks2 = k0 ^ k1 ^ 0x1BD11BDAu;
    x0 += ks0; x1 += ks1;
#define TF_R4(a, b, c, d)                                 \
    x0 += x1; x1 = rotl32(x1, a); x1 ^= x0;               \
    x0 += x1; x1 = rotl32(x1, b); x1 ^= x0;               \
    x0 += x1; x1 = rotl32(x1, c); x1 ^= x0;               \
    x0 += x1; x1 = rotl32(x1, d); x1 ^= x0;
    TF_R4(13, 15, 26, 6);  x0 += ks1; x1 += ks2 + 1u;
    TF_R4(17, 29, 16, 24); x0 += ks2; x1 += ks0 + 2u;
    TF_R4(13, 15, 26, 6);  x0 += ks0; x1 += ks1 + 3u;
    TF_R4(17, 29, 16, 24); x0 += ks1; x1 += ks2 + 4u;
    TF_R4(13, 15, 26, 6);  x0 += ks2; x1 += ks0 + 5u;
#undef TF_R4
    o0 = x0; o1 = x1;
}

// keep[j] (JAX default: threefry_partitionable, 32-bit): bit31(b1^b2)==0, x=(0,j).
__device__ __forceinline__ bool drop_keep(unsigned int j) {
    unsigned int o0, o1;
    threefry2x32(0u, 42u, 0u, j, o0, o1);
    return ((o0 ^ o1) & 0x80000000u) == 0u;
}

// ---------------- gather layer1 (128 feats) + bias + relu + dropout ----------------
__global__ void gather128_fused_kernel(const float* __restrict__ H,
                                       const float* __restrict__ b,
                                       float* __restrict__ out) {
    int gwarp = (blockIdx.x * blockDim.x + threadIdx.x) >> 5;
    int lane = threadIdx.x & 31;
    int nwarp = (gridDim.x * blockDim.x) >> 5;
    const float4* __restrict__ H4 = (const float4*)H;
    float4 bv = ((const float4*)b)[lane];
    for (int d = gwarp; d < NN; d += nwarp) {
        float dd = g_dinv[d];
        float4 hv = H4[(size_t)d * 32 + lane];
        float4 acc = make_float4(dd * hv.x, dd * hv.y, dd * hv.z, dd * hv.w);
        int i = g_off[d], s1 = g_off[d + 1];
        for (; i + 4 <= s1; i += 4) {
            int a0 = g_csr[i], a1 = g_csr[i + 1], a2 = g_csr[i + 2], a3 = g_csr[i + 3];
            float w0 = g_csrw[i], w1 = g_csrw[i + 1], w2 = g_csrw[i + 2], w3 = g_csrw[i + 3];
            float4 v0 = H4[(size_t)a0 * 32 + lane];
            float4 v1 = H4[(size_t)a1 * 32 + lane];
            float4 v2 = H4[(size_t)a2 * 32 + lane];
            float4 v3 = H4[(size_t)a3 * 32 + lane];
            acc.x += w0 * v0.x + w1 * v1.x + w2 * v2.x + w3 * v3.x;
            acc.y += w0 * v0.y + w1 * v1.y + w2 * v2.y + w3 * v3.y;
            acc.z += w0 * v0.z + w1 * v1.z + w2 * v2.z + w3 * v3.z;
            acc.w += w0 * v0.w + w1 * v1.w + w2 * v2.w + w3 * v3.w;
        }
        for (; i < s1; i++) {
            int s = g_csr[i];
            float w = g_csrw[i];
            float4 v = H4[(size_t)s * 32 + lane];
            acc.x += w * v.x; acc.y += w * v.y; acc.z += w * v.z; acc.w += w * v.w;
        }
        // epilogue: *dd, +b1, relu, dropout(p=0.5, x2 on keep)
        unsigned int j = (unsigned int)d * 128u + (unsigned int)lane * 4u;
        acc.x = fmaxf(fmaf(dd, acc.x, bv.x), 0.f);
        acc.y = fmaxf(fmaf(dd, acc.y, bv.y), 0.f);
        acc.z = fmaxf(fmaf(dd, acc.z, bv.z), 0.f);
        acc.w = fmaxf(fmaf(dd, acc.w, bv.w), 0.f);
        acc.x = drop_keep(j + 0u) ? 2.f * acc.x : 0.f;
        acc.y = drop_keep(j + 1u) ? 2.f * acc.y : 0.f;
        acc.z = drop_keep(j + 2u) ? 2.f * acc.z : 0.f;
        acc.w = drop_keep(j + 3u) ? 2.f * acc.w : 0.f;
        ((float4*)out)[(size_t)d * 32 + lane] = acc;
    }
}

// ---------------- gather layer2 (64 feats) + b2 -> d_out ----------------
__global__ void gather64_kernel(const float* __restrict__ H, const float* __restrict__ b,
                                float* __restrict__ out) {
    int gwarp = (blockIdx.x * blockDim.x + threadIdx.x) >> 5;
    int lane = threadIdx.x & 31;
    int nwarp = (gridDim.x * blockDim.x) >> 5;
    const float2* __restrict__ H2 = (const float2*)H;
    float2 bv = ((const float2*)b)[lane];
    for (int d = gwarp; d < NN; d += nwarp) {
        float dd = g_dinv[d];
        float2 hv = H2[(size_t)d * 32 + lane];
        float2 acc = make_float2(dd * hv.x, dd * hv.y);
        int i = g_off[d], s1 = g_off[d + 1];
        for (; i + 4 <= s1; i += 4) {
            int a0 = g_csr[i], a1 = g_csr[i + 1], a2 = g_csr[i + 2], a3 = g_csr[i + 3];
            float w0 = g_csrw[i], w1 = g_csrw[i + 1], w2 = g_csrw[i + 2], w3 = g_csrw[i + 3];
            float2 v0 = H2[(size_t)a0 * 32 + lane];
            float2 v1 = H2[(size_t)a1 * 32 + lane];
            float2 v2 = H2[(size_t)a2 * 32 + lane];
            float2 v3 = H2[(size_t)a3 * 32 + lane];
            acc.x += w0 * v0.x + w1 * v1.x + w2 * v2.x + w3 * v3.x;
            acc.y += w0 * v0.y + w1 * v1.y + w2 * v2.y + w3 * v3.y;
        }
        for (; i < s1; i++) {
            int s = g_csr[i];
            float w = g_csrw[i];
            float2 v = H2[(size_t)s * 32 + lane];
            acc.x += w * v.x; acc.y += w * v.y;
        }
        acc.x = fmaf(dd, acc.x, bv.x);
        acc.y = fmaf(dd, acc.y, bv.y);
        ((float2*)out)[(size_t)d * 32 + lane] = acc;
    }
}

// ---------------- launch ----------------
extern "C" void kernel_launch(void* const* d_in, const int* in_sizes, int n_in,
                              void* d_out, int out_size) {
    // One-time side-stream + events (created on first, uncaptured, correctness call;
    // deterministic work every call).
    static cudaStream_t s2 = 0;
    static cudaEvent_t ev_fork = 0, ev_join = 0;
    if (!s2) {
        cudaStreamCreateWithFlags(&s2, cudaStreamNonBlocking);
        cudaEventCreateWithFlags(&ev_fork, cudaEventDisableTiming);
        cudaEventCreateWithFlags(&ev_join, cudaEventDisableTiming);
    }

    // Map inputs by element count (all distinct).
    const float* x  = 0; const void* ei = 0;
    const float* W1 = 0; const float* b1 = 0;
    const float* W2 = 0; const float* b2 = 0;
    for (int i = 0; i < n_in; i++) {
        switch (in_sizes[i]) {
            case NN * NF:  x  = (const float*)d_in[i]; break;
            case 2 * NE:   ei = d_in[i];               break;
            case NF * NH:  W1 = (const float*)d_in[i]; break;
            case NH:       b1 = (const float*)d_in[i]; break;
            case NH * NC:  W2 = (const float*)d_in[i]; break;
            case NC:       b2 = (const float*)d_in[i]; break;
        }
    }
    float* out = (float*)d_out;

    float* H1; cudaGetSymbolAddress((void**)&H1, g_H1);
    float* A1; cudaGetSymbolAddress((void**)&A1, g_A1);
    float* H2; cudaGetSymbolAddress((void**)&H2, g_H2);

    // Fork: CSR build on s2, GEMM1 on main stream, concurrently.
    cudaEventRecord(ev_fork, 0);
    cudaStreamWaitEvent(s2, ev_fork, 0);

    zero_counts_kernel<<<(NN + 255) / 256, 256, 0, s2>>>();
    convert_hist_kernel<<<2048, 256, 0, s2>>>(ei);
    scan_kernel<<<1, 1024, 0, s2>>>();
    fill_kernel<<<1024, 256, 0, s2>>>();
    cudaEventRecord(ev_join, s2);

    gemm_f32x2_kernel<NH><<<(NN + 127) / 128, 256>>>(x, W1, H1, NN, NF);

    // Join: gather needs both CSR and H1.
    cudaStreamWaitEvent(0, ev_join, 0);

    gather128_fused_kernel<<<2048, 256>>>(H1, b1, A1);
    gemm_f32x2_kernel<NC><<<(NN + 127) / 128, 256>>>(A1, W2, H2, NN, NH);
    gather64_kernel<<<1024, 256>>>(H2, b2, out);
}

// round 9
// speedup vs baseline: 1.4632x; 1.3271x over previous
#include <cuda_runtime.h>
#include <cuda_bf16.h>
#include <stdint.h>

// Problem constants
#define NN 50000
#define NE 800000
#define NF 256
#define NH 128
#define NC 64

// ============================ device scratch ============================
__device__ int   g_edges[2 * NE];
__device__ int   g_counts[NN];
__device__ int   g_off[NN + 1];
__device__ int   g_cursor[NN];
__device__ int   g_csr[NE];
__device__ float g_csrw[NE];
__device__ float g_dinv[NN];
__device__ float g_H1[NN * NH];
__device__ float g_A1[NN * NH];
__device__ float g_H2[NN * NC];
__device__ __nv_bfloat16 g_B1h[NH * NF], g_B1l[NH * NF];   // W1^T split: [N][K], K-contig
__device__ __nv_bfloat16 g_B2h[NC * NH], g_B2l[NC * NH];   // W2^T split

// ============================ CSR build ============================
__global__ void zero_counts_kernel() {
    int tid = blockIdx.x * blockDim.x + threadIdx.x;
    if (tid < NN) g_counts[tid] = 0;
}

__global__ void convert_hist_kernel(const void* ein) {
    const unsigned int* e32 = (const unsigned int*)ein;
    bool is64 = true;
#pragma unroll
    for (int i = 0; i < 8; i++) {
        if (e32[2 * i + 1] != 0u) { is64 = false; break; }
    }
    int i = blockIdx.x * blockDim.x + threadIdx.x;
    if (i >= 2 * NE) return;
    int v = is64 ? (int)((const long long*)ein)[i] : ((const int*)ein)[i];
    g_edges[i] = v;
    if (i >= NE) atomicAdd(&g_counts[v], 1);
}

__global__ void scan_kernel() {
    __shared__ int sh[1024];
    const int t = threadIdx.x;
    const int per = (NN + 1023) >> 10;
    int lo = t * per;
    int hi = lo + per; if (hi > NN) hi = NN;
    if (lo > NN) lo = NN;
    int s = 0;
    for (int i = lo; i < hi; i++) s += g_counts[i];
    sh[t] = s;
    __syncthreads();
    for (int off = 1; off < 1024; off <<= 1) {
        int v = (t >= off) ? sh[t - off] : 0;
        __syncthreads();
        sh[t] += v;
        __syncthreads();
    }
    int base = (t > 0) ? sh[t - 1] : 0;
    for (int i = lo; i < hi; i++) {
        g_off[i] = base;
        g_cursor[i] = base;
        base += g_counts[i];
        g_dinv[i] = rsqrtf((float)(g_counts[i] + 1));
    }
    if (t == 1023) g_off[NN] = sh[1023];
}

__global__ void fill_kernel() {
    int e = blockIdx.x * blockDim.x + threadIdx.x;
    if (e >= NE) return;
    int d = g_edges[NE + e];
    int s = g_edges[e];
    int p = atomicAdd(&g_cursor[d], 1);
    g_csr[p] = s;
    g_csrw[p] = g_dinv[s];
}

// ============================ weight prep: W[K,N] -> B[N,K] bf16 hi/lo ============================
template <int K, int N>
__global__ void wprep_kernel(const float* __restrict__ W,
                             __nv_bfloat16* __restrict__ bh, __nv_bfloat16* __restrict__ bl) {
    int i = blockIdx.x * blockDim.x + threadIdx.x;
    if (i >= N * K) return;
    int n = i / K, k = i % K;
    float f = W[k * N + n];
    __nv_bfloat16 h = __float2bfloat16_rn(f);
    float lo = f - __bfloat162float(h);
    bh[i] = h;
    bl[i] = __float2bfloat16_rn(lo);
}

// ============================ mma.sync bf16x3 GEMM ============================
__device__ __forceinline__ void mma_bf16(float* c,
                                         uint32_t a0, uint32_t a1, uint32_t a2, uint32_t a3,
                                         uint32_t b0, uint32_t b1) {
    asm volatile(
        "mma.sync.aligned.m16n8k16.row.col.f32.bf16.bf16.f32 "
        "{%0,%1,%2,%3}, {%4,%5,%6,%7}, {%8,%9}, {%0,%1,%2,%3};"
        : "+f"(c[0]), "+f"(c[1]), "+f"(c[2]), "+f"(c[3])
        : "r"(a0), "r"(a1), "r"(a2), "r"(a3), "r"(b0), "r"(b1));
}

// C[M,BN] = A[M,K] @ W[K,BN]; W pre-split bf16 [BN][K].
// 3 products: Ah*Bh + Ah*Bl + Al*Bh. BM=128, BK=32, 256 threads (8 warps).
template <int BN, int K>
__global__ __launch_bounds__(256) void gemm_mma_kernel(
    const float* __restrict__ A,
    const __nv_bfloat16* __restrict__ Bh, const __nv_bfloat16* __restrict__ Bl,
    float* __restrict__ C, int M)
{
    constexpr int BM = 128, BK = 32;
    constexpr int LDA = 40;                       // padded row (80B = 20-bank stride, conflict-free)
    constexpr int WARPS_M = (BN == 128) ? 2 : 4;
    constexpr int WARPS_N = 8 / WARPS_M;
    constexpr int MT = BM / (WARPS_M * 16);       // m-tiles per warp
    constexpr int NT = BN / (WARPS_N * 8);        // n-tiles per warp

    __shared__ unsigned short Ah[BM * LDA], Al[BM * LDA];
    __shared__ unsigned short Bsh[BN * LDA], Bsl[BN * LDA];

    const int tid = threadIdx.x;
    const int wid = tid >> 5;
    const int lane = tid & 31;
    const int g = lane >> 2;
    const int tig = lane & 3;
    const int warp_m = wid % WARPS_M;
    const int warp_n = wid / WARPS_M;
    const int wm0 = warp_m * MT * 16;
    const int wn0 = warp_n * NT * 8;
    const int row0 = blockIdx.x * BM;

    float acc[MT][NT][4];
#pragma unroll
    for (int mt = 0; mt < MT; mt++)
#pragma unroll
        for (int nt = 0; nt < NT; nt++)
#pragma unroll
            for (int i = 0; i < 4; i++) acc[mt][nt][i] = 0.f;

    for (int kc = 0; kc < K; kc += BK) {
        __syncthreads();
        // ---- A chunk: fp32 -> bf16 hi/lo in smem ----
#pragma unroll
        for (int l = 0; l < (BM * BK) / (256 * 4); l++) {  // 4 float4 per thread
            int idx = l * 256 + tid;
            int r = idx >> 3;
            int kq = (idx & 7) * 4;
            float4 f = make_float4(0.f, 0.f, 0.f, 0.f);
            if (row0 + r < M) f = *(const float4*)&A[(size_t)(row0 + r) * K + kc + kq];
            __nv_bfloat162 h0 = __float22bfloat162_rn(make_float2(f.x, f.y));
            __nv_bfloat162 h1 = __float22bfloat162_rn(make_float2(f.z, f.w));
            float2 hb0 = __bfloat1622float2(h0);
            float2 hb1 = __bfloat1622float2(h1);
            __nv_bfloat162 l0 = __float22bfloat162_rn(make_float2(f.x - hb0.x, f.y - hb0.y));
            __nv_bfloat162 l1 = __float22bfloat162_rn(make_float2(f.z - hb1.x, f.w - hb1.y));
            *(uint32_t*)&Ah[r * LDA + kq]     = *(uint32_t*)&h0;
            *(uint32_t*)&Ah[r * LDA + kq + 2] = *(uint32_t*)&h1;
            *(uint32_t*)&Al[r * LDA + kq]     = *(uint32_t*)&l0;
            *(uint32_t*)&Al[r * LDA + kq + 2] = *(uint32_t*)&l1;
        }
        // ---- B chunk: bf16 [BN][K] -> smem ----
#pragma unroll
        for (int l = 0; l < (BN * BK) / (256 * 8); l++) {  // uint4 = 8 bf16
            int idx = l * 256 + tid;
            int n = idx >> 2;
            int kq = (idx & 3) * 8;
            *(uint4*)&Bsh[n * LDA + kq] = *(const uint4*)&Bh[(size_t)n * K + kc + kq];
            *(uint4*)&Bsl[n * LDA + kq] = *(const uint4*)&Bl[(size_t)n * K + kc + kq];
        }
        __syncthreads();

#pragma unroll
        for (int kk = 0; kk < BK; kk += 16) {
            uint32_t af[MT][4], bfh[NT][2], bfl[NT][2];
#pragma unroll
            for (int mt = 0; mt < MT; mt++) {
                int r0 = wm0 + mt * 16 + g;
                af[mt][0] = *(const uint32_t*)&Ah[r0 * LDA + kk + tig * 2];
                af[mt][1] = *(const uint32_t*)&Ah[(r0 + 8) * LDA + kk + tig * 2];
                af[mt][2] = *(const uint32_t*)&Ah[r0 * LDA + kk + 8 + tig * 2];
                af[mt][3] = *(const uint32_t*)&Ah[(r0 + 8) * LDA + kk + 8 + tig * 2];
            }
#pragma unroll
            for (int nt = 0; nt < NT; nt++) {
                int n0 = wn0 + nt * 8 + g;
                bfh[nt][0] = *(const uint32_t*)&Bsh[n0 * LDA + kk + tig * 2];
                bfh[nt][1] = *(const uint32_t*)&Bsh[n0 * LDA + kk + 8 + tig * 2];
                bfl[nt][0] = *(const uint32_t*)&Bsl[n0 * LDA + kk + tig * 2];
                bfl[nt][1] = *(const uint32_t*)&Bsl[n0 * LDA + kk + 8 + tig * 2];
            }
            // Ah*Bh and Ah*Bl
#pragma unroll
            for (int mt = 0; mt < MT; mt++)
#pragma unroll
                for (int nt = 0; nt < NT; nt++) {
                    mma_bf16(acc[mt][nt], af[mt][0], af[mt][1], af[mt][2], af[mt][3],
                             bfh[nt][0], bfh[nt][1]);
                    mma_bf16(acc[mt][nt], af[mt][0], af[mt][1], af[mt][2], af[mt][3],
                             bfl[nt][0], bfl[nt][1]);
                }
            // Al*Bh (reuse af regs)
#pragma unroll
            for (int mt = 0; mt < MT; mt++) {
                int r0 = wm0 + mt * 16 + g;
                af[mt][0] = *(const uint32_t*)&Al[r0 * LDA + kk + tig * 2];
                af[mt][1] = *(const uint32_t*)&Al[(r0 + 8) * LDA + kk + tig * 2];
                af[mt][2] = *(const uint32_t*)&Al[r0 * LDA + kk + 8 + tig * 2];
                af[mt][3] = *(const uint32_t*)&Al[(r0 + 8) * LDA + kk + 8 + tig * 2];
            }
#pragma unroll
            for (int mt = 0; mt < MT; mt++)
#pragma unroll
                for (int nt = 0; nt < NT; nt++)
                    mma_bf16(acc[mt][nt], af[mt][0], af[mt][1], af[mt][2], af[mt][3],
                             bfh[nt][0], bfh[nt][1]);
        }
    }

    // ---- epilogue: fragment -> gmem (float2 per row-half) ----
#pragma unroll
    for (int mt = 0; mt < MT; mt++) {
        int r0 = row0 + wm0 + mt * 16 + g;
#pragma unroll
        for (int nt = 0; nt < NT; nt++) {
            int c0 = wn0 + nt * 8 + tig * 2;
            if (r0 < M)
                *(float2*)&C[(size_t)r0 * BN + c0] = make_float2(acc[mt][nt][0], acc[mt][nt][1]);
            if (r0 + 8 < M)
                *(float2*)&C[(size_t)(r0 + 8) * BN + c0] = make_float2(acc[mt][nt][2], acc[mt][nt][3]);
        }
    }
}

// ============================ Threefry + dropout ============================
__device__ __forceinline__ unsigned int rotl32(unsigned int x, int d) {
    return (x << d) | (x >> (32 - d));
}
__device__ __forceinline__ void threefry2x32(unsigned int k0, unsigned int k1,
                                             unsigned int x0, unsigned int x1,
                                             unsigned int& o0, unsigned int& o1) {
    unsigned int ks0 = k0, ks1 = k1, ks2 = k0 ^ k1 ^ 0x1BD11BDAu;
    x0 += ks0; x1 += ks1;
#define TF_R4(a, b, c, d)                                 \
    x0 += x1; x1 = rotl32(x1, a); x1 ^= x0;               \
    x0 += x1; x1 = rotl32(x1, b); x1 ^= x0;               \
    x0 += x1; x1 = rotl32(x1, c); x1 ^= x0;               \
    x0 += x1; x1 = rotl32(x1, d); x1 ^= x0;
    TF_R4(13, 15, 26, 6);  x0 += ks1; x1 += ks2 + 1u;
    TF_R4(17, 29, 16, 24); x0 += ks2; x1 += ks0 + 2u;
    TF_R4(13, 15, 26, 6);  x0 += ks0; x1 += ks1 + 3u;
    TF_R4(17, 29, 16, 24); x0 += ks1; x1 += ks2 + 4u;
    TF_R4(13, 15, 26, 6);  x0 += ks2; x1 += ks0 + 5u;
#undef TF_R4
    o0 = x0; o1 = x1;
}
// keep[j]: bit31(b1^b2)==0 for threefry2x32((0,42),(0,j)) — JAX partitionable 32-bit.
__device__ __forceinline__ bool drop_keep(unsigned int j) {
    unsigned int o0, o1;
    threefry2x32(0u, 42u, 0u, j, o0, o1);
    return ((o0 ^ o1) & 0x80000000u) == 0u;
}

// ============================ gathers ============================
__global__ void gather128_fused_kernel(const float* __restrict__ H,
                                       const float* __restrict__ b,
                                       float* __restrict__ out) {
    int gwarp = (blockIdx.x * blockDim.x + threadIdx.x) >> 5;
    int lane = threadIdx.x & 31;
    int nwarp = (gridDim.x * blockDim.x) >> 5;
    const float4* __restrict__ H4 = (const float4*)H;
    float4 bv = ((const float4*)b)[lane];
    for (int d = gwarp; d < NN; d += nwarp) {
        float dd = g_dinv[d];
        float4 hv = H4[(size_t)d * 32 + lane];
        float4 acc = make_float4(dd * hv.x, dd * hv.y, dd * hv.z, dd * hv.w);
        int i = g_off[d], s1 = g_off[d + 1];
        for (; i + 4 <= s1; i += 4) {
            int a0 = g_csr[i], a1 = g_csr[i + 1], a2 = g_csr[i + 2], a3 = g_csr[i + 3];
            float w0 = g_csrw[i], w1 = g_csrw[i + 1], w2 = g_csrw[i + 2], w3 = g_csrw[i + 3];
            float4 v0 = H4[(size_t)a0 * 32 + lane];
            float4 v1 = H4[(size_t)a1 * 32 + lane];
            float4 v2 = H4[(size_t)a2 * 32 + lane];
            float4 v3 = H4[(size_t)a3 * 32 + lane];
            acc.x += w0 * v0.x + w1 * v1.x + w2 * v2.x + w3 * v3.x;
            acc.y += w0 * v0.y + w1 * v1.y + w2 * v2.y + w3 * v3.y;
            acc.z += w0 * v0.z + w1 * v1.z + w2 * v2.z + w3 * v3.z;
            acc.w += w0 * v0.w + w1 * v1.w + w2 * v2.w + w3 * v3.w;
        }
        for (; i < s1; i++) {
            int s = g_csr[i];
            float w = g_csrw[i];
            float4 v = H4[(size_t)s * 32 + lane];
            acc.x += w * v.x; acc.y += w * v.y; acc.z += w * v.z; acc.w += w * v.w;
        }
        unsigned int j = (unsigned int)d * 128u + (unsigned int)lane * 4u;
        acc.x = fmaxf(fmaf(dd, acc.x, bv.x), 0.f);
        acc.y = fmaxf(fmaf(dd, acc.y, bv.y), 0.f);
        acc.z = fmaxf(fmaf(dd, acc.z, bv.z), 0.f);
        acc.w = fmaxf(fmaf(dd, acc.w, bv.w), 0.f);
        acc.x = drop_keep(j + 0u) ? 2.f * acc.x : 0.f;
        acc.y = drop_keep(j + 1u) ? 2.f * acc.y : 0.f;
        acc.z = drop_keep(j + 2u) ? 2.f * acc.z : 0.f;
        acc.w = drop_keep(j + 3u) ? 2.f * acc.w : 0.f;
        ((float4*)out)[(size_t)d * 32 + lane] = acc;
    }
}

__global__ void gather64_kernel(const float* __restrict__ H, const float* __restrict__ b,
                                float* __restrict__ out) {
    int gwarp = (blockIdx.x * blockDim.x + threadIdx.x) >> 5;
    int lane = threadIdx.x & 31;
    int nwarp = (gridDim.x * blockDim.x) >> 5;
    const float2* __restrict__ H2 = (const float2*)H;
    float2 bv = ((const float2*)b)[lane];
    for (int d = gwarp; d < NN; d += nwarp) {
        float dd = g_dinv[d];
        float2 hv = H2[(size_t)d * 32 + lane];
        float2 acc = make_float2(dd * hv.x, dd * hv.y);
        int i = g_off[d], s1 = g_off[d + 1];
        for (; i + 4 <= s1; i += 4) {
            int a0 = g_csr[i], a1 = g_csr[i + 1], a2 = g_csr[i + 2], a3 = g_csr[i + 3];
            float w0 = g_csrw[i], w1 = g_csrw[i + 1], w2 = g_csrw[i + 2], w3 = g_csrw[i + 3];
            float2 v0 = H2[(size_t)a0 * 32 + lane];
            float2 v1 = H2[(size_t)a1 * 32 + lane];
            float2 v2 = H2[(size_t)a2 * 32 + lane];
            float2 v3 = H2[(size_t)a3 * 32 + lane];
            acc.x += w0 * v0.x + w1 * v1.x + w2 * v2.x + w3 * v3.x;
            acc.y += w0 * v0.y + w1 * v1.y + w2 * v2.y + w3 * v3.y;
        }
        for (; i < s1; i++) {
            int s = g_csr[i];
            float w = g_csrw[i];
            float2 v = H2[(size_t)s * 32 + lane];
            acc.x += w * v.x; acc.y += w * v.y;
        }
        acc.x = fmaf(dd, acc.x, bv.x);
        acc.y = fmaf(dd, acc.y, bv.y);
        ((float2*)out)[(size_t)d * 32 + lane] = acc;
    }
}

// ============================ launch ============================
extern "C" void kernel_launch(void* const* d_in, const int* in_sizes, int n_in,
                              void* d_out, int out_size) {
    static cudaStream_t s2 = 0;
    static cudaEvent_t ev_fork = 0, ev_join = 0;
    if (!s2) {
        cudaStreamCreateWithFlags(&s2, cudaStreamNonBlocking);
        cudaEventCreateWithFlags(&ev_fork, cudaEventDisableTiming);
        cudaEventCreateWithFlags(&ev_join, cudaEventDisableTiming);
    }

    const float* x  = 0; const void* ei = 0;
    const float* W1 = 0; const float* b1 = 0;
    const float* W2 = 0; const float* b2 = 0;
    for (int i = 0; i < n_in; i++) {
        switch (in_sizes[i]) {
            case NN * NF:  x  = (const float*)d_in[i]; break;
            case 2 * NE:   ei = d_in[i];               break;
            case NF * NH:  W1 = (const float*)d_in[i]; break;
            case NH:       b1 = (const float*)d_in[i]; break;
            case NH * NC:  W2 = (const float*)d_in[i]; break;
            case NC:       b2 = (const float*)d_in[i]; break;
        }
    }
    float* out = (float*)d_out;

    float* H1; cudaGetSymbolAddress((void**)&H1, g_H1);
    float* A1; cudaGetSymbolAddress((void**)&A1, g_A1);
    float* H2; cudaGetSymbolAddress((void**)&H2, g_H2);
    __nv_bfloat16 *B1h, *B1l, *B2h, *B2l;
    cudaGetSymbolAddress((void**)&B1h, g_B1h);
    cudaGetSymbolAddress((void**)&B1l, g_B1l);
    cudaGetSymbolAddress((void**)&B2h, g_B2h);
    cudaGetSymbolAddress((void**)&B2l, g_B2l);

    // Fork: CSR build on s2; weight prep + GEMM1 on main stream.
    cudaEventRecord(ev_fork, 0);
    cudaStreamWaitEvent(s2, ev_fork, 0);

    zero_counts_kernel<<<(NN + 255) / 256, 256, 0, s2>>>();
    convert_hist_kernel<<<(2 * NE + 255) / 256, 256, 0, s2>>>(ei);
    scan_kernel<<<1, 1024, 0, s2>>>();
    fill_kernel<<<(NE + 255) / 256, 256, 0, s2>>>();
    cudaEventRecord(ev_join, s2);

    wprep_kernel<NF, NH><<<(NH * NF + 255) / 256, 256>>>(W1, B1h, B1l);
    wprep_kernel<NH, NC><<<(NC * NH + 255) / 256, 256>>>(W2, B2h, B2l);
    gemm_mma_kernel<NH, NF><<<(NN + 127) / 128, 256>>>(x, B1h, B1l, H1, NN);

    cudaStreamWaitEvent(0, ev_join, 0);

    gather128_fused_kernel<<<2048, 256>>>(H1, b1, A1);
    gemm_mma_kernel<NC, NH><<<(NN + 127) / 128, 256>>>(A1, B2h, B2l, H2, NN);
    gather64_kernel<<<1024, 256>>>(H2, b2, out);
}